// round 11
// baseline (speedup 1.0000x reference)
#include <cuda_runtime.h>
#include <cuda_fp16.h>
#include <cstdint>

#define DINLINE __device__ __forceinline__

// ============================================================================
// KAN layer as one fp16 tensor-core GEMM.
//   out = clip(silu(x) @ BW^T + einsum('bik,oik->bo', bspline(x), SW), -1, 1)
// Rewritten as A[8192, 12288] @ W[1024, 12288]^T with k = i*12 + j:
//   A[b, i*12+j] = bspline_j(x[b,i]) (j<11) | silu(x[b,i]) (j=11)
//   W[o, i*12+j] = SW[o,i,j] * 1024    (j<11) | BW[o,i] * 1024  (j=11)
// W pre-scaled x1024 (weights ~U(-1/1024,1/1024)) to avoid fp16 subnormals;
// epilogue multiplies by 1/1024. fp32 accumulation throughout.
// tcgen05 path rejected by harness ptxas (targets sm_103, not sm_103a) ->
// mma.sync.m16n8k16 HMMA path (all instructions baseline sm_80 PTX).
// Audited to fixpoint rounds 4-6: fragment layouts vs PTX ISA spec, cp.async
// group accounting, slot-reuse race, swizzle/alignment, register budget.
// Round-9/10 note: fused A-generation (basis-major k-blocks, x-subtile SMEM
// reuse across 12 j's) is fully specified and gated on the first profile
// showing lts__throughput as the binder; it loses if issue/tensor-bound.
// ============================================================================

// ---------------- problem constants ----------------
constexpr int BATCH = 8192;
constexpr int INF   = 1024;
constexpr int OUTF  = 1024;
constexpr int K12   = 12;              // 11 spline bases + 1 silu/base slot
constexpr int KDIM  = INF * K12;       // 12288
constexpr float WSCALE     = 1024.0f;
constexpr float INV_WSCALE = 1.0f / 1024.0f;

// ---------------- GEMM tiling ----------------
constexpr int TM = 128;                // CTA M tile
constexpr int TN = 256;                // CTA N tile
constexpr int TK = 64;                 // K per stage (64 fp16 = 128B row, SW128 native)
constexpr int STAGES = 4;
constexpr int A_TILE_B = TM * TK * 2;  // 16 KB
constexpr int W_TILE_B = TN * TK * 2;  // 32 KB
constexpr int STAGE_B  = A_TILE_B + W_TILE_B;  // 48 KB
constexpr int SMEM_DYN = STAGES * STAGE_B + 1024;  // 193 KB (+align slack)
constexpr int NKI = KDIM / TK;         // 192 K iterations
constexpr int NTHREADS = 256;          // 8 warps: 2 (M) x 4 (N), warp tile 64x64

// ---------------- scratch (static device globals; no allocs) ----------------
__device__ __align__(128) __half g_A[(size_t)BATCH * KDIM];   // 201 MB fp16 activations
__device__ __align__(128) __half g_W[(size_t)OUTF  * KDIM];   // 24 MB fp16 weights (x1024)

// ---------------- helpers ----------------
DINLINE uint32_t smem_u32(const void* p) {
    uint32_t a;
    asm("{ .reg .u64 t; cvta.to.shared.u64 t, %1; cvt.u32.u64 %0, t; }" : "=r"(a) : "l"(p));
    return a;
}
DINLINE void cp_async16(uint32_t saddr, const void* gptr) {
    asm volatile("cp.async.cg.shared.global [%0], [%1], 16;" :: "r"(saddr), "l"(gptr));
}
#define CP_COMMIT() asm volatile("cp.async.commit_group;" ::: "memory")
#define CP_WAIT2()  asm volatile("cp.async.wait_group 2;"  ::: "memory")

DINLINE uint32_t sw128(uint32_t off) { return off ^ ((off >> 3) & 0x70); }

DINLINE void ldsm_x4(uint32_t* r, uint32_t addr) {
    asm volatile("ldmatrix.sync.aligned.m8n8.x4.shared.b16 {%0,%1,%2,%3}, [%4];"
                 : "=r"(r[0]), "=r"(r[1]), "=r"(r[2]), "=r"(r[3]) : "r"(addr));
}
DINLINE void mma16816(float* c, const uint32_t* a, uint32_t b0, uint32_t b1) {
    asm volatile(
        "mma.sync.aligned.m16n8k16.row.col.f32.f16.f16.f32 "
        "{%0,%1,%2,%3}, {%4,%5,%6,%7}, {%8,%9}, {%0,%1,%2,%3};"
        : "+f"(c[0]), "+f"(c[1]), "+f"(c[2]), "+f"(c[3])
        : "r"(a[0]), "r"(a[1]), "r"(a[2]), "r"(a[3]), "r"(b0), "r"(b1));
}

// ---------------- packing math shared by prep kernels ----------------
DINLINE void pack12_from_x(float xv, uint32_t* words) {
    __half vals[12];
#pragma unroll
    for (int j = 0; j < 11; j++) {
        float c = -1.25f + 0.25f * (float)j;
        float u = fabsf(xv - c) * 4.0f;                // /GRID_STEP
        float c2 = 2.0f - u, c1 = 1.0f - u;
        float v;
        if (u < 1.0f)      v = (1.0f / 6.0f) * (c2 * c2 * c2 - 4.0f * c1 * c1 * c1);
        else if (u < 2.0f) v = (1.0f / 6.0f) * (c2 * c2 * c2);
        else               v = 0.0f;
        vals[j] = __float2half_rn(v);
    }
    vals[11] = __float2half_rn(xv / (1.0f + __expf(-xv)));   // silu
    const uint32_t* src = reinterpret_cast<const uint32_t*>(vals);
#pragma unroll
    for (int t = 0; t < 6; t++) words[t] = src[t];
}

// ---------------- prep kernel: activations -> fp16 packed A ----------------
// SMEM-staged so 24B/elem rows leave as fully-coalesced 16B stores
// (direct strided STG.32 costs ~6x write amplification at L2/DRAM).
__global__ void __launch_bounds__(256) gen_A_kernel(const float* __restrict__ x) {
    __shared__ uint32_t stage[256 * 6];                // 6 KB
    int base = blockIdx.x * 256;                       // BATCH*INF % 256 == 0
    float xv = x[base + threadIdx.x];
    uint32_t w[6];
    pack12_from_x(xv, w);
#pragma unroll
    for (int t = 0; t < 6; t++) stage[threadIdx.x * 6 + t] = w[t];
    __syncthreads();
    uint4* dst = reinterpret_cast<uint4*>(g_A + (size_t)base * K12);
    const uint4* src = reinterpret_cast<const uint4*>(stage);
#pragma unroll
    for (int i = threadIdx.x; i < 256 * 6 / 4; i += 256) dst[i] = src[i];
}

// ---------------- prep kernel: weights -> fp16 packed W (x1024) ----------------
__global__ void __launch_bounds__(256) gen_W_kernel(const float* __restrict__ bw,
                                                    const float* __restrict__ sw) {
    __shared__ uint32_t stage[256 * 6];
    int base = blockIdx.x * 256;                       // OUTF*INF % 256 == 0
    int idx = base + threadIdx.x;
    const float* sp = sw + (size_t)idx * 11;           // strided reads absorbed by L1
    __half vals[12];
#pragma unroll
    for (int j = 0; j < 11; j++) vals[j] = __float2half_rn(sp[j] * WSCALE);
    vals[11] = __float2half_rn(bw[idx] * WSCALE);
    const uint32_t* src32 = reinterpret_cast<const uint32_t*>(vals);
#pragma unroll
    for (int t = 0; t < 6; t++) stage[threadIdx.x * 6 + t] = src32[t];
    __syncthreads();
    uint4* dst = reinterpret_cast<uint4*>(g_W + (size_t)base * K12);
    const uint4* src = reinterpret_cast<const uint4*>(stage);
#pragma unroll
    for (int i = threadIdx.x; i < 256 * 6 / 4; i += 256) dst[i] = src[i];
}

// ---------------- GEMM stage loader ----------------
DINLINE void load_stage(uint32_t tiles, int slot, int blk, int tid,
                        const __half* Ag, const __half* Wg) {
    uint32_t a_s = tiles + slot * STAGE_B;
    uint32_t w_s = a_s + A_TILE_B;
    int k0 = blk * TK;
    // A tile: TM rows x 128B (8 x 16B chunks per row): 1024 chunks / 256 thr = 4
#pragma unroll
    for (int i = tid; i < TM * 8; i += NTHREADS) {
        int r = i >> 3, c = i & 7;
        uint32_t off = (uint32_t)(r * 128 + c * 16);
        cp_async16(a_s + sw128(off), Ag + (size_t)r * KDIM + k0 + c * 8);
    }
    // W tile: TN rows x 128B: 2048 chunks / 256 thr = 8
#pragma unroll
    for (int i = tid; i < TN * 8; i += NTHREADS) {
        int r = i >> 3, c = i & 7;
        uint32_t off = (uint32_t)(r * 128 + c * 16);
        cp_async16(w_s + sw128(off), Wg + (size_t)r * KDIM + k0 + c * 8);
    }
}

// ---------------- main GEMM kernel (mma.sync m16n8k16) ----------------
__global__ void __launch_bounds__(NTHREADS, 1) kan_gemm_kernel(float* __restrict__ out) {
    extern __shared__ char smem[];
    uint32_t sbase = smem_u32(smem);
    uint32_t tiles = (sbase + 1023u) & ~1023u;        // 1024B-aligned tile region
    int tid = threadIdx.x, lane = tid & 31, wid = tid >> 5;
    int warp_m = wid & 1;                              // 0..1 -> 64-row slice
    int warp_n = wid >> 1;                             // 0..3 -> 64-col slice
    int m0 = blockIdx.y * TM;
    int n0 = blockIdx.x * TN;

    const __half* Ag = g_A + (size_t)m0 * KDIM;
    const __half* Wg = g_W + (size_t)n0 * KDIM;

    float c[4][8][4];                                  // [mt][nt][frag] = 128 regs
#pragma unroll
    for (int i = 0; i < 4; i++)
#pragma unroll
        for (int j = 0; j < 8; j++)
#pragma unroll
            for (int q = 0; q < 4; q++) c[i][j][q] = 0.0f;

    // per-thread ldmatrix row/col offsets (within warp tile)
    int a_row = (lane & 15);                 // +mt*16
    int a_colg = (lane >> 4) * 8;            // k sub-block
    int b_row = (lane & 7) + ((lane >> 4) & 1) * 8;   // +nt2*16
    int b_colg = ((lane >> 3) & 1) * 8;      // k sub-block

    // prologue: stages 0..2
#pragma unroll
    for (int s = 0; s < STAGES - 1; s++) { load_stage(tiles, s, s, tid, Ag, Wg); CP_COMMIT(); }

    for (int t = 0; t < NKI; t++) {
        CP_WAIT2();                                    // stage t landed (<=2 groups pending)
        __syncthreads();                               // all warps done reading slot (t-1)&3

        // issue next refill BEFORE compute: lengthens the load latency window
        // by the whole tile-compute block (slot (t+3)&3 == (t-1)&3 is free now)
        int nb = t + STAGES - 1;
        if (nb < NKI) load_stage(tiles, nb & 3, nb, tid, Ag, Wg);
        CP_COMMIT();                                   // uniform group accounting

        uint32_t a_s = tiles + (t & 3) * STAGE_B;
        uint32_t w_s = a_s + A_TILE_B;

#pragma unroll
        for (int kk = 0; kk < 4; kk++) {               // 4 x K16 within TK=64
            int k0 = kk * 16;
            uint32_t a[4][4], b[4][4];
#pragma unroll
            for (int mt = 0; mt < 4; mt++) {
                uint32_t off = (uint32_t)((warp_m * 64 + mt * 16 + a_row) * 128 + (k0 + a_colg) * 2);
                ldsm_x4(a[mt], a_s + sw128(off));
            }
#pragma unroll
            for (int nt2 = 0; nt2 < 4; nt2++) {
                uint32_t off = (uint32_t)((warp_n * 64 + nt2 * 16 + b_row) * 128 + (k0 + b_colg) * 2);
                ldsm_x4(b[nt2], w_s + sw128(off));
            }
#pragma unroll
            for (int mt = 0; mt < 4; mt++)
#pragma unroll
                for (int nt2 = 0; nt2 < 4; nt2++) {
                    mma16816(c[mt][nt2 * 2],     a[mt], b[nt2][0], b[nt2][1]);
                    mma16816(c[mt][nt2 * 2 + 1], a[mt], b[nt2][2], b[nt2][3]);
                }
        }
    }

    // epilogue: scale, clip, store (float2 per fragment half)
    int gr = lane >> 2, gc = (lane & 3) * 2;
#pragma unroll
    for (int mt = 0; mt < 4; mt++) {
#pragma unroll
        for (int nt = 0; nt < 8; nt++) {
            int row = m0 + warp_m * 64 + mt * 16 + gr;
            int col = n0 + warp_n * 64 + nt * 8 + gc;
            float2 v0, v1;
            v0.x = fminf(fmaxf(c[mt][nt][0] * INV_WSCALE, -1.0f), 1.0f);
            v0.y = fminf(fmaxf(c[mt][nt][1] * INV_WSCALE, -1.0f), 1.0f);
            v1.x = fminf(fmaxf(c[mt][nt][2] * INV_WSCALE, -1.0f), 1.0f);
            v1.y = fminf(fmaxf(c[mt][nt][3] * INV_WSCALE, -1.0f), 1.0f);
            *reinterpret_cast<float2*>(out + (size_t)row * OUTF + col) = v0;
            *reinterpret_cast<float2*>(out + (size_t)(row + 8) * OUTF + col) = v1;
        }
    }
}

// ---------------- launch ----------------
extern "C" void kernel_launch(void* const* d_in, const int* in_sizes, int n_in,
                              void* d_out, int out_size) {
    const float* x  = (const float*)d_in[0];   // [8192, 1024]
    const float* bw = (const float*)d_in[1];   // [1024, 1024]
    const float* sw = (const float*)d_in[2];   // [1024, 1024, 11]
    float* out = (float*)d_out;                // [8192, 1024]

    gen_A_kernel<<<BATCH * INF / 256, 256>>>(x);
    gen_W_kernel<<<OUTF * INF / 256, 256>>>(bw, sw);

    cudaFuncSetAttribute(kan_gemm_kernel,
                         cudaFuncAttributeMaxDynamicSharedMemorySize, SMEM_DYN);
    dim3 grid(OUTF / TN, BATCH / TM);          // (4, 64) = 256 CTAs
    kan_gemm_kernel<<<grid, NTHREADS, SMEM_DYN>>>(out);
}